// round 6
// baseline (speedup 1.0000x reference)
#include <cuda_runtime.h>
#include <cuda_fp16.h>
#include <math.h>
#include <stdint.h>

// Problem constants
#define BATCH 2
#define NB    9216          // H*W per batch (96*96)
#define NPIX  (BATCH * NB)  // 18432
#define CIN   384
#define C1    256
#define C2    128
#define MASK_THR 0.2f

// Scratch (device globals: no allocations allowed)
__device__ float  g_h1[(size_t)C1 * NPIX];     // [o][n]
__device__ float  g_feat[(size_t)NPIX * C2];   // [n][c]
__device__ float  g_rf[(size_t)NPIX * C2];     // [n][c] normalized fp32
__device__ __align__(256) __half g_hih[(size_t)NPIX * C2]; // fp16 hi part
__device__ __align__(256) __half g_loh[(size_t)NPIX * C2]; // fp16 residual
// per-half top-2 candidates: [half][row][slot]
__device__ float  g_t2v[2 * NPIX * 2];
__device__ int    g_t2i[2 * NPIX * 2];

// ---------------------------------------------------------------------------
// PTX helpers (baseline ISA only — compute_103 safe)
// ---------------------------------------------------------------------------
__device__ __forceinline__ uint32_t smem_u32(const void* p) {
    return (uint32_t)__cvta_generic_to_shared(p);
}
#define CP16(dst, src) \
    asm volatile("cp.async.cg.shared.global [%0], [%1], 16;" :: "r"(dst), "l"(src))
#define CPCOMMIT() asm volatile("cp.async.commit_group;")
#define CPWAIT0()  asm volatile("cp.async.wait_group 0;" ::: "memory")

#define LDSM4(r0, r1, r2, r3, addr) \
    asm volatile("ldmatrix.sync.aligned.m8n8.x4.shared.b16 {%0,%1,%2,%3}, [%4];" \
        : "=r"(r0), "=r"(r1), "=r"(r2), "=r"(r3) : "r"(addr))

#define MMA16816(c, a, b) \
    asm volatile("mma.sync.aligned.m16n8k16.row.col.f32.f16.f16.f32 " \
        "{%0,%1,%2,%3}, {%4,%5,%6,%7}, {%8,%9}, {%0,%1,%2,%3};" \
        : "+f"((c)[0]), "+f"((c)[1]), "+f"((c)[2]), "+f"((c)[3]) \
        : "r"((a)[0]), "r"((a)[1]), "r"((a)[2]), "r"((a)[3]), \
          "r"((b)[0]), "r"((b)[1]))

// ---------------------------------------------------------------------------
// GEMM1: g_h1[o][n] = relu( sum_k W1[o][k] * X[b][k][hw] + b1[o] )
// ---------------------------------------------------------------------------
__global__ void gemm1_kernel(const float* __restrict__ X,
                             const float* __restrict__ W1,
                             const float* __restrict__ b1v) {
    __shared__ float Ws[64 * 16];
    __shared__ float Xs[16 * 64];
    const int t  = threadIdx.x;
    const int tx = t & 15, ty = t >> 4;
    const int n0 = blockIdx.x * 64;
    const int o0 = blockIdx.y * 64;
    const int b  = n0 / NB;
    const int hw0 = n0 % NB;
    const float* Xb = X + (size_t)b * CIN * NB;

    float acc[4][4];
#pragma unroll
    for (int i = 0; i < 4; i++)
#pragma unroll
        for (int j = 0; j < 4; j++) acc[i][j] = 0.f;

    const int lo = t >> 2, lq = t & 3;
    const int lk = t >> 4, ln4 = t & 15;

    for (int k0 = 0; k0 < CIN; k0 += 16) {
        float4 w = *(const float4*)&W1[(size_t)(o0 + lo) * CIN + k0 + lq * 4];
        *(float4*)&Ws[lo * 16 + lq * 4] = w;
        float4 x = *(const float4*)&Xb[(size_t)(k0 + lk) * NB + hw0 + ln4 * 4];
        *(float4*)&Xs[lk * 64 + ln4 * 4] = x;
        __syncthreads();
#pragma unroll
        for (int k4 = 0; k4 < 4; k4++) {
            float4 w0 = *(const float4*)&Ws[(ty * 4 + 0) * 16 + k4 * 4];
            float4 w1 = *(const float4*)&Ws[(ty * 4 + 1) * 16 + k4 * 4];
            float4 w2 = *(const float4*)&Ws[(ty * 4 + 2) * 16 + k4 * 4];
            float4 w3 = *(const float4*)&Ws[(ty * 4 + 3) * 16 + k4 * 4];
            const float* wp0 = (const float*)&w0;
            const float* wp1 = (const float*)&w1;
            const float* wp2 = (const float*)&w2;
            const float* wp3 = (const float*)&w3;
#pragma unroll
            for (int kk = 0; kk < 4; kk++) {
                float4 xv = *(const float4*)&Xs[(k4 * 4 + kk) * 64 + tx * 4];
                float a0 = wp0[kk], a1 = wp1[kk], a2 = wp2[kk], a3 = wp3[kk];
                acc[0][0] += a0 * xv.x; acc[0][1] += a0 * xv.y; acc[0][2] += a0 * xv.z; acc[0][3] += a0 * xv.w;
                acc[1][0] += a1 * xv.x; acc[1][1] += a1 * xv.y; acc[1][2] += a1 * xv.z; acc[1][3] += a1 * xv.w;
                acc[2][0] += a2 * xv.x; acc[2][1] += a2 * xv.y; acc[2][2] += a2 * xv.z; acc[2][3] += a2 * xv.w;
                acc[3][0] += a3 * xv.x; acc[3][1] += a3 * xv.y; acc[3][2] += a3 * xv.z; acc[3][3] += a3 * xv.w;
            }
        }
        __syncthreads();
    }
#pragma unroll
    for (int i = 0; i < 4; i++) {
        int o = o0 + ty * 4 + i;
        float bias = b1v[o];
        float4 r;
        r.x = fmaxf(acc[i][0] + bias, 0.f);
        r.y = fmaxf(acc[i][1] + bias, 0.f);
        r.z = fmaxf(acc[i][2] + bias, 0.f);
        r.w = fmaxf(acc[i][3] + bias, 0.f);
        *(float4*)&g_h1[(size_t)o * NPIX + n0 + tx * 4] = r;
    }
}

// ---------------------------------------------------------------------------
// GEMM2: g_feat[n][o] = sum_k W2[o][k] * g_h1[k][n] + b2[o]
// ---------------------------------------------------------------------------
__global__ void gemm2_kernel(const float* __restrict__ W2,
                             const float* __restrict__ b2v) {
    __shared__ float Ws[64 * 16];
    __shared__ float Hs[16 * 64];
    const int t  = threadIdx.x;
    const int tx = t & 15, ty = t >> 4;
    const int n0 = blockIdx.x * 64;
    const int o0 = blockIdx.y * 64;

    float acc[4][4];
#pragma unroll
    for (int i = 0; i < 4; i++)
#pragma unroll
        for (int j = 0; j < 4; j++) acc[i][j] = 0.f;

    const int lo = t >> 2, lq = t & 3;
    const int lk = t >> 4, ln4 = t & 15;

    for (int k0 = 0; k0 < C1; k0 += 16) {
        float4 w = *(const float4*)&W2[(size_t)(o0 + lo) * C1 + k0 + lq * 4];
        *(float4*)&Ws[lo * 16 + lq * 4] = w;
        float4 h = *(const float4*)&g_h1[(size_t)(k0 + lk) * NPIX + n0 + ln4 * 4];
        *(float4*)&Hs[lk * 64 + ln4 * 4] = h;
        __syncthreads();
#pragma unroll
        for (int k4 = 0; k4 < 4; k4++) {
            float4 w0 = *(const float4*)&Ws[(ty * 4 + 0) * 16 + k4 * 4];
            float4 w1 = *(const float4*)&Ws[(ty * 4 + 1) * 16 + k4 * 4];
            float4 w2 = *(const float4*)&Ws[(ty * 4 + 2) * 16 + k4 * 4];
            float4 w3 = *(const float4*)&Ws[(ty * 4 + 3) * 16 + k4 * 4];
            const float* wp0 = (const float*)&w0;
            const float* wp1 = (const float*)&w1;
            const float* wp2 = (const float*)&w2;
            const float* wp3 = (const float*)&w3;
#pragma unroll
            for (int kk = 0; kk < 4; kk++) {
                float4 xv = *(const float4*)&Hs[(k4 * 4 + kk) * 64 + tx * 4];
                float a0 = wp0[kk], a1 = wp1[kk], a2 = wp2[kk], a3 = wp3[kk];
                acc[0][0] += a0 * xv.x; acc[0][1] += a0 * xv.y; acc[0][2] += a0 * xv.z; acc[0][3] += a0 * xv.w;
                acc[1][0] += a1 * xv.x; acc[1][1] += a1 * xv.y; acc[1][2] += a1 * xv.z; acc[1][3] += a1 * xv.w;
                acc[2][0] += a2 * xv.x; acc[2][1] += a2 * xv.y; acc[2][2] += a2 * xv.z; acc[2][3] += a2 * xv.w;
                acc[3][0] += a3 * xv.x; acc[3][1] += a3 * xv.y; acc[3][2] += a3 * xv.z; acc[3][3] += a3 * xv.w;
            }
        }
        __syncthreads();
    }
    float bias[4];
#pragma unroll
    for (int i = 0; i < 4; i++) bias[i] = b2v[o0 + ty * 4 + i];
#pragma unroll
    for (int j = 0; j < 4; j++) {
        int n = n0 + tx * 4 + j;
        float4 r;
        r.x = acc[0][j] + bias[0];
        r.y = acc[1][j] + bias[1];
        r.z = acc[2][j] + bias[2];
        r.w = acc[3][j] + bias[3];
        *(float4*)&g_feat[(size_t)n * C2 + o0 + ty * 4] = r;
    }
}

// ---------------------------------------------------------------------------
// Normalize: rf = feat / max(||feat||, 1e-12); fp32 rf + fp16 hi/lo split.
// ---------------------------------------------------------------------------
__global__ void normalize_kernel() {
    const int n = blockIdx.x;
    const int c = threadIdx.x;
    float v = g_feat[(size_t)n * C2 + c];
    float s = v * v;
#pragma unroll
    for (int off = 16; off; off >>= 1) s += __shfl_xor_sync(0xffffffffu, s, off);
    __shared__ float ws[4];
    if ((c & 31) == 0) ws[c >> 5] = s;
    __syncthreads();
    float tot = ws[0] + ws[1] + ws[2] + ws[3];
    float norm = sqrtf(tot);
    float nf = v / fmaxf(norm, 1e-12f);
    g_rf[(size_t)n * C2 + c] = nf;
    __half hi = __float2half_rn(nf);
    g_hih[(size_t)n * C2 + c] = hi;
    g_loh[(size_t)n * C2 + c] = __float2half_rn(nf - __half2float(hi));
}

// ---------------------------------------------------------------------------
// Top-2 insert with jax top_k tie-breaking (equal value -> lower index).
// ---------------------------------------------------------------------------
__device__ __forceinline__ void ins2(float v, int j,
                                     float& v1, int& i1, float& v2, int& i2) {
    if (v > v1 || (v == v1 && j < i1)) {
        v2 = v1; i2 = i1; v1 = v; i1 = j;
    } else if (v > v2 || (v == v2 && j < i2)) {
        v2 = v; i2 = j;
    }
}

// ---------------------------------------------------------------------------
// Tensor-core (mma.sync fp16 3-term) similarity + top-2, M=32/warp version.
// Grid: (36 i-tiles, 2 j-halves, 2 batches) = 144 CTAs -> 1 CTA/SM.
// CTA: 256 thr (8 warps), i-tile 256 rows (warp w owns rows 32w..32w+31 as
// two m16 rowgroups). A-hi fragments register-resident (64 regs); A-lo kept
// in 64KB smem and streamed per k-step (2 LDSM/ks). B hi/lo double-buffered
// (2 x 32KB) via cp.async.  D = Ah*Bh' + Al*Bh' + Ah*Bl'  (fp32 acc).
// 16 independent accumulator chains per thread hide HMMA latency at
// 2 warps/SMSP; LDS/HMMA cycle ratio drops 67% -> 42% vs M=16 version.
// ---------------------------------------------------------------------------
#define JT    64
#define JHALF (NB / 2)             // 4608
#define NTJ2  (JHALF / JT)         // 72
#define AL_BYTES 65536             // A-lo resident: 256 rows x 256B
#define BUFB  32768                // one B buffer: hi 16KB + lo 16KB
#define SIM_SMEM (AL_BYTES + 2 * BUFB)   // 128KB

__device__ __forceinline__ uint32_t sw_off(int r, int c) {
    // row r (256B rows), 16B chunk c, XOR swizzle on chunk index
    return (uint32_t)(r * 256 + ((c ^ (r & 7)) << 4));
}

__global__ void __launch_bounds__(256, 1) sim_mma_kernel() {
    extern __shared__ __align__(1024) char sm[];
    const int t = threadIdx.x;
    const int w = t >> 5, l = t & 31;
    const int jh = blockIdx.y;
    const int b  = blockIdx.z;
    const int i0 = blockIdx.x * 256;
    const int jbase = jh * JHALF;
    const __half* Hsrc = g_hih + (size_t)b * NB * C2;
    const __half* Lsrc = g_loh + (size_t)b * NB * C2;
    const uint32_t sb = smem_u32(sm);          // A-lo region
    const uint32_t bb0 = sb + AL_BYTES;        // B buffers

    // ---- Stage A-lo (resident) and A-hi (into B region, temporary) ----
#pragma unroll
    for (int e = 0; e < 16; e++) {
        int id = e * 256 + t;          // 0..4095 : 256 rows x 16 chunks
        int r = id >> 4, c = id & 15;
        uint32_t o = sw_off(r, c);
        CP16(sb + o,  (const char*)(Lsrc + (size_t)(i0 + r) * C2) + c * 16);
        CP16(bb0 + o, (const char*)(Hsrc + (size_t)(i0 + r) * C2) + c * 16);
    }
    CPCOMMIT(); CPWAIT0();
    __syncthreads();

    // ---- A-hi fragments (register resident): [rowgroup][ks][4] ----
    const int sub = l >> 3;
    const int arl = ((sub & 1) << 3) + (l & 7);
    const int cb  = sub >> 1;
    uint32_t a_hi[2][8][4];
#pragma unroll
    for (int rg = 0; rg < 2; rg++)
#pragma unroll
        for (int ks = 0; ks < 8; ks++) {
            uint32_t ad = bb0 + sw_off(w * 32 + rg * 16 + arl, ks * 2 + cb);
            LDSM4(a_hi[rg][ks][0], a_hi[rg][ks][1],
                  a_hi[rg][ks][2], a_hi[rg][ks][3], ad);
        }
    __syncthreads();   // B region free for streaming now

    // B-tile ldmatrix address pieces (per thread)
    const int brn = ((sub >> 1) << 3) + (l & 7);   // row within 16-row group
    const int bcb = sub & 1;                       // k-chunk select

    // ---- prefetch B tile 0 into buffer 0 ----
#pragma unroll
    for (int e = 0; e < 4; e++) {
        int id = e * 256 + t;      // 0..1023 : 64 rows x 16 chunks
        int r = id >> 4, c = id & 15;
        uint32_t o = sw_off(r, c);
        CP16(bb0 + o,         (const char*)(Hsrc + (size_t)(jbase + r) * C2) + c * 16);
        CP16(bb0 + 16384 + o, (const char*)(Lsrc + (size_t)(jbase + r) * C2) + c * 16);
    }
    CPCOMMIT();

    // top-2 state: 4 row-slots/thread:
    //   s=0: rg0 row (l>>2); s=1: rg0 row (l>>2)+8; s=2,3: rg1 same
    float v1[4], v2[4]; int i1[4], i2[4];
#pragma unroll
    for (int s = 0; s < 4; s++) {
        v1[s] = -INFINITY; v2[s] = -INFINITY;
        i1[s] = 0x7fffffff; i2[s] = 0x7fffffff;
    }

    for (int jt = 0; jt < NTJ2; jt++) {
        CPWAIT0();
        __syncthreads();

        // prefetch next tile into other buffer (overlaps compute)
        if (jt + 1 < NTJ2) {
            const int j0n = jbase + (jt + 1) * JT;
            const uint32_t bo = bb0 + (uint32_t)((jt + 1) & 1) * BUFB;
#pragma unroll
            for (int e = 0; e < 4; e++) {
                int id = e * 256 + t;
                int r = id >> 4, c = id & 15;
                uint32_t o = bo + sw_off(r, c);
                CP16(o,         (const char*)(Hsrc + (size_t)(j0n + r) * C2) + c * 16);
                CP16(o + 16384, (const char*)(Lsrc + (size_t)(j0n + r) * C2) + c * 16);
            }
            CPCOMMIT();
        }

        const uint32_t bo = bb0 + (uint32_t)(jt & 1) * BUFB;
        float acc[2][8][4];
#pragma unroll
        for (int rg = 0; rg < 2; rg++)
#pragma unroll
            for (int nf = 0; nf < 8; nf++)
#pragma unroll
                for (int q = 0; q < 4; q++) acc[rg][nf][q] = 0.f;

#pragma unroll
        for (int ks = 0; ks < 8; ks++) {
            const int ck = ks * 2;
            // stream A-lo fragments for this k-step (both rowgroups)
            uint32_t al0[4], al1[4];
            LDSM4(al0[0], al0[1], al0[2], al0[3],
                  sb + sw_off(w * 32 + arl, ck + cb));
            LDSM4(al1[0], al1[1], al1[2], al1[3],
                  sb + sw_off(w * 32 + 16 + arl, ck + cb));
#pragma unroll
            for (int nb = 0; nb < 4; nb++) {
                uint32_t bh0, bh1, bh2, bh3, bl0, bl1, bl2, bl3;
                uint32_t ad = bo + sw_off(nb * 16 + brn, ck + bcb);
                LDSM4(bh0, bh1, bh2, bh3, ad);
                LDSM4(bl0, bl1, bl2, bl3, ad + 16384);
                uint32_t bhA[2] = {bh0, bh1}, bhB[2] = {bh2, bh3};
                uint32_t blA[2] = {bl0, bl1}, blB[2] = {bl2, bl3};
                MMA16816(acc[0][2 * nb],     a_hi[0][ks], bhA);
                MMA16816(acc[0][2 * nb + 1], a_hi[0][ks], bhB);
                MMA16816(acc[1][2 * nb],     a_hi[1][ks], bhA);
                MMA16816(acc[1][2 * nb + 1], a_hi[1][ks], bhB);
                MMA16816(acc[0][2 * nb],     al0, bhA);
                MMA16816(acc[0][2 * nb + 1], al0, bhB);
                MMA16816(acc[1][2 * nb],     al1, bhA);
                MMA16816(acc[1][2 * nb + 1], al1, bhB);
                MMA16816(acc[0][2 * nb],     a_hi[0][ks], blA);
                MMA16816(acc[0][2 * nb + 1], a_hi[0][ks], blB);
                MMA16816(acc[1][2 * nb],     a_hi[1][ks], blA);
                MMA16816(acc[1][2 * nb + 1], a_hi[1][ks], blB);
            }
        }

        // ---- fold tile into running top-2 (guarded by max-tree) ----
        const int cbase = jbase + jt * JT + (l & 3) * 2;
#pragma unroll
        for (int rg = 0; rg < 2; rg++) {
            float mA = fmaxf(acc[rg][0][0], acc[rg][0][1]);
            float mB = fmaxf(acc[rg][0][2], acc[rg][0][3]);
#pragma unroll
            for (int nf = 1; nf < 8; nf++) {
                mA = fmaxf(mA, fmaxf(acc[rg][nf][0], acc[rg][nf][1]));
                mB = fmaxf(mB, fmaxf(acc[rg][nf][2], acc[rg][nf][3]));
            }
            const int sA = rg * 2, sB = rg * 2 + 1;
            if (mA >= v2[sA]) {
#pragma unroll
                for (int nf = 0; nf < 8; nf++) {
                    ins2(acc[rg][nf][0], cbase + nf * 8,     v1[sA], i1[sA], v2[sA], i2[sA]);
                    ins2(acc[rg][nf][1], cbase + nf * 8 + 1, v1[sA], i1[sA], v2[sA], i2[sA]);
                }
            }
            if (mB >= v2[sB]) {
#pragma unroll
                for (int nf = 0; nf < 8; nf++) {
                    ins2(acc[rg][nf][2], cbase + nf * 8,     v1[sB], i1[sB], v2[sB], i2[sB]);
                    ins2(acc[rg][nf][3], cbase + nf * 8 + 1, v1[sB], i1[sB], v2[sB], i2[sB]);
                }
            }
        }
    }

    // ---- merge across the 4 lanes (l&3) sharing each row ----
#pragma unroll
    for (int s = 0; s < 4; s++) {
#pragma unroll
        for (int off = 1; off <= 2; off <<= 1) {
            float ov1 = __shfl_xor_sync(0xffffffffu, v1[s], off);
            int   oi1 = __shfl_xor_sync(0xffffffffu, i1[s], off);
            float ov2 = __shfl_xor_sync(0xffffffffu, v2[s], off);
            int   oi2 = __shfl_xor_sync(0xffffffffu, i2[s], off);
            ins2(ov1, oi1, v1[s], i1[s], v2[s], i2[s]);
            ins2(ov2, oi2, v1[s], i1[s], v2[s], i2[s]);
        }
    }
    if ((l & 3) == 0) {
#pragma unroll
        for (int s = 0; s < 4; s++) {
            const int rg = s >> 1;
            const int row = b * NB + i0 + w * 32 + rg * 16 + ((s & 1) << 3) + (l >> 2);
            const size_t p = ((size_t)jh * NPIX + row) * 2;
            g_t2v[p]     = v1[s]; g_t2i[p]     = i1[s];
            g_t2v[p + 1] = v2[s]; g_t2i[p + 1] = i2[s];
        }
    }
}

// ---------------------------------------------------------------------------
// Merge j-halves + distance + mask (exact fp32 recompute, matches reference).
// ---------------------------------------------------------------------------
__global__ void dist_kernel(float* __restrict__ out) {
    const int gw   = (int)((blockIdx.x * blockDim.x + threadIdx.x) >> 5);
    const int lane = threadIdx.x & 31;
    if (gw >= NPIX) return;
    const int b = gw / NB;
    int nn = 0;
    if (lane == 0) {
        float v1 = -INFINITY, v2 = -INFINITY;
        int   i1 = 0x7fffffff, i2 = 0x7fffffff;
#pragma unroll
        for (int h = 0; h < 2; h++) {
            const size_t p = ((size_t)h * NPIX + gw) * 2;
            ins2(g_t2v[p],     g_t2i[p],     v1, i1, v2, i2);
            ins2(g_t2v[p + 1], g_t2i[p + 1], v1, i1, v2, i2);
        }
        nn = i2;
    }
    nn = __shfl_sync(0xffffffffu, nn, 0);
    const float* a = g_rf + (size_t)gw * C2;
    const float* c = g_rf + (size_t)(b * NB + nn) * C2;
    float4 av = *(const float4*)&a[lane * 4];
    float4 cv = *(const float4*)&c[lane * 4];
    float dx = av.x - cv.x, dy = av.y - cv.y, dz = av.z - cv.z, dw = av.w - cv.w;
    float s = dx * dx + dy * dy + dz * dz + dw * dw;
#pragma unroll
    for (int off = 16; off; off >>= 1) s += __shfl_xor_sync(0xffffffffu, s, off);
    if (lane == 0) {
        float d = sqrtf(s);
        out[NPIX + gw] = d;
        out[gw] = (d > MASK_THR) ? 1.0f : 0.0f;
    }
}

// ---------------------------------------------------------------------------
extern "C" void kernel_launch(void* const* d_in, const int* in_sizes, int n_in,
                              void* d_out, int out_size) {
    const float* features = (const float*)d_in[0];
    const float* W1 = (const float*)d_in[1];
    const float* b1 = (const float*)d_in[2];
    const float* W2 = (const float*)d_in[3];
    const float* b2 = (const float*)d_in[4];
    float* out = (float*)d_out;

    cudaFuncSetAttribute(sim_mma_kernel,
                         cudaFuncAttributeMaxDynamicSharedMemorySize, SIM_SMEM);

    gemm1_kernel<<<dim3(NPIX / 64, C1 / 64), 256>>>(features, W1, b1);
    gemm2_kernel<<<dim3(NPIX / 64, C2 / 64), 256>>>(W2, b2);
    normalize_kernel<<<NPIX, 128>>>();
    sim_mma_kernel<<<dim3(NB / 256, 2, BATCH), 256, SIM_SMEM>>>();
    dist_kernel<<<(NPIX * 32 + 255) / 256, 256>>>(out);
}

// round 7
// speedup vs baseline: 1.2688x; 1.2688x over previous
#include <cuda_runtime.h>
#include <cuda_fp16.h>
#include <math.h>
#include <stdint.h>

// Problem constants
#define BATCH 2
#define NB    9216          // H*W per batch (96*96)
#define NPIX  (BATCH * NB)  // 18432
#define CIN   384
#define C1    256
#define C2    128
#define MASK_THR 0.2f

// Scratch (device globals: no allocations allowed)
__device__ float  g_h1[(size_t)C1 * NPIX];     // [o][n]
__device__ float  g_feat[(size_t)NPIX * C2];   // [n][c]
__device__ float  g_rf[(size_t)NPIX * C2];     // [n][c] normalized fp32
__device__ __align__(256) __half g_hih[(size_t)NPIX * C2]; // fp16 hi part
__device__ __align__(256) __half g_loh[(size_t)NPIX * C2]; // fp16 residual
// per-half top-2 candidates: [half][row][slot]
__device__ float  g_t2v[2 * NPIX * 2];
__device__ int    g_t2i[2 * NPIX * 2];

// ---------------------------------------------------------------------------
// PTX helpers (baseline ISA only — compute_103 safe)
// ---------------------------------------------------------------------------
__device__ __forceinline__ uint32_t smem_u32(const void* p) {
    return (uint32_t)__cvta_generic_to_shared(p);
}
#define CP16(dst, src) \
    asm volatile("cp.async.cg.shared.global [%0], [%1], 16;" :: "r"(dst), "l"(src))
#define CPCOMMIT() asm volatile("cp.async.commit_group;")
#define CPWAIT0()  asm volatile("cp.async.wait_group 0;" ::: "memory")

#define LDSM4(r0, r1, r2, r3, addr) \
    asm volatile("ldmatrix.sync.aligned.m8n8.x4.shared.b16 {%0,%1,%2,%3}, [%4];" \
        : "=r"(r0), "=r"(r1), "=r"(r2), "=r"(r3) : "r"(addr))

#define MMA16816(c, a, b) \
    asm volatile("mma.sync.aligned.m16n8k16.row.col.f32.f16.f16.f32 " \
        "{%0,%1,%2,%3}, {%4,%5,%6,%7}, {%8,%9}, {%0,%1,%2,%3};" \
        : "+f"((c)[0]), "+f"((c)[1]), "+f"((c)[2]), "+f"((c)[3]) \
        : "r"((a)[0]), "r"((a)[1]), "r"((a)[2]), "r"((a)[3]), \
          "r"((b)[0]), "r"((b)[1]))

// ---------------------------------------------------------------------------
// GEMM1: g_h1[o][n] = relu( sum_k W1[o][k] * X[b][k][hw] + b1[o] )
// ---------------------------------------------------------------------------
__global__ void gemm1_kernel(const float* __restrict__ X,
                             const float* __restrict__ W1,
                             const float* __restrict__ b1v) {
    __shared__ float Ws[64 * 16];
    __shared__ float Xs[16 * 64];
    const int t  = threadIdx.x;
    const int tx = t & 15, ty = t >> 4;
    const int n0 = blockIdx.x * 64;
    const int o0 = blockIdx.y * 64;
    const int b  = n0 / NB;
    const int hw0 = n0 % NB;
    const float* Xb = X + (size_t)b * CIN * NB;

    float acc[4][4];
#pragma unroll
    for (int i = 0; i < 4; i++)
#pragma unroll
        for (int j = 0; j < 4; j++) acc[i][j] = 0.f;

    const int lo = t >> 2, lq = t & 3;
    const int lk = t >> 4, ln4 = t & 15;

    for (int k0 = 0; k0 < CIN; k0 += 16) {
        float4 w = *(const float4*)&W1[(size_t)(o0 + lo) * CIN + k0 + lq * 4];
        *(float4*)&Ws[lo * 16 + lq * 4] = w;
        float4 x = *(const float4*)&Xb[(size_t)(k0 + lk) * NB + hw0 + ln4 * 4];
        *(float4*)&Xs[lk * 64 + ln4 * 4] = x;
        __syncthreads();
#pragma unroll
        for (int k4 = 0; k4 < 4; k4++) {
            float4 w0 = *(const float4*)&Ws[(ty * 4 + 0) * 16 + k4 * 4];
            float4 w1 = *(const float4*)&Ws[(ty * 4 + 1) * 16 + k4 * 4];
            float4 w2 = *(const float4*)&Ws[(ty * 4 + 2) * 16 + k4 * 4];
            float4 w3 = *(const float4*)&Ws[(ty * 4 + 3) * 16 + k4 * 4];
            const float* wp0 = (const float*)&w0;
            const float* wp1 = (const float*)&w1;
            const float* wp2 = (const float*)&w2;
            const float* wp3 = (const float*)&w3;
#pragma unroll
            for (int kk = 0; kk < 4; kk++) {
                float4 xv = *(const float4*)&Xs[(k4 * 4 + kk) * 64 + tx * 4];
                float a0 = wp0[kk], a1 = wp1[kk], a2 = wp2[kk], a3 = wp3[kk];
                acc[0][0] += a0 * xv.x; acc[0][1] += a0 * xv.y; acc[0][2] += a0 * xv.z; acc[0][3] += a0 * xv.w;
                acc[1][0] += a1 * xv.x; acc[1][1] += a1 * xv.y; acc[1][2] += a1 * xv.z; acc[1][3] += a1 * xv.w;
                acc[2][0] += a2 * xv.x; acc[2][1] += a2 * xv.y; acc[2][2] += a2 * xv.z; acc[2][3] += a2 * xv.w;
                acc[3][0] += a3 * xv.x; acc[3][1] += a3 * xv.y; acc[3][2] += a3 * xv.z; acc[3][3] += a3 * xv.w;
            }
        }
        __syncthreads();
    }
#pragma unroll
    for (int i = 0; i < 4; i++) {
        int o = o0 + ty * 4 + i;
        float bias = b1v[o];
        float4 r;
        r.x = fmaxf(acc[i][0] + bias, 0.f);
        r.y = fmaxf(acc[i][1] + bias, 0.f);
        r.z = fmaxf(acc[i][2] + bias, 0.f);
        r.w = fmaxf(acc[i][3] + bias, 0.f);
        *(float4*)&g_h1[(size_t)o * NPIX + n0 + tx * 4] = r;
    }
}

// ---------------------------------------------------------------------------
// GEMM2: g_feat[n][o] = sum_k W2[o][k] * g_h1[k][n] + b2[o]
// ---------------------------------------------------------------------------
__global__ void gemm2_kernel(const float* __restrict__ W2,
                             const float* __restrict__ b2v) {
    __shared__ float Ws[64 * 16];
    __shared__ float Hs[16 * 64];
    const int t  = threadIdx.x;
    const int tx = t & 15, ty = t >> 4;
    const int n0 = blockIdx.x * 64;
    const int o0 = blockIdx.y * 64;

    float acc[4][4];
#pragma unroll
    for (int i = 0; i < 4; i++)
#pragma unroll
        for (int j = 0; j < 4; j++) acc[i][j] = 0.f;

    const int lo = t >> 2, lq = t & 3;
    const int lk = t >> 4, ln4 = t & 15;

    for (int k0 = 0; k0 < C1; k0 += 16) {
        float4 w = *(const float4*)&W2[(size_t)(o0 + lo) * C1 + k0 + lq * 4];
        *(float4*)&Ws[lo * 16 + lq * 4] = w;
        float4 h = *(const float4*)&g_h1[(size_t)(k0 + lk) * NPIX + n0 + ln4 * 4];
        *(float4*)&Hs[lk * 64 + ln4 * 4] = h;
        __syncthreads();
#pragma unroll
        for (int k4 = 0; k4 < 4; k4++) {
            float4 w0 = *(const float4*)&Ws[(ty * 4 + 0) * 16 + k4 * 4];
            float4 w1 = *(const float4*)&Ws[(ty * 4 + 1) * 16 + k4 * 4];
            float4 w2 = *(const float4*)&Ws[(ty * 4 + 2) * 16 + k4 * 4];
            float4 w3 = *(const float4*)&Ws[(ty * 4 + 3) * 16 + k4 * 4];
            const float* wp0 = (const float*)&w0;
            const float* wp1 = (const float*)&w1;
            const float* wp2 = (const float*)&w2;
            const float* wp3 = (const float*)&w3;
#pragma unroll
            for (int kk = 0; kk < 4; kk++) {
                float4 xv = *(const float4*)&Hs[(k4 * 4 + kk) * 64 + tx * 4];
                float a0 = wp0[kk], a1 = wp1[kk], a2 = wp2[kk], a3 = wp3[kk];
                acc[0][0] += a0 * xv.x; acc[0][1] += a0 * xv.y; acc[0][2] += a0 * xv.z; acc[0][3] += a0 * xv.w;
                acc[1][0] += a1 * xv.x; acc[1][1] += a1 * xv.y; acc[1][2] += a1 * xv.z; acc[1][3] += a1 * xv.w;
                acc[2][0] += a2 * xv.x; acc[2][1] += a2 * xv.y; acc[2][2] += a2 * xv.z; acc[2][3] += a2 * xv.w;
                acc[3][0] += a3 * xv.x; acc[3][1] += a3 * xv.y; acc[3][2] += a3 * xv.z; acc[3][3] += a3 * xv.w;
            }
        }
        __syncthreads();
    }
    float bias[4];
#pragma unroll
    for (int i = 0; i < 4; i++) bias[i] = b2v[o0 + ty * 4 + i];
#pragma unroll
    for (int j = 0; j < 4; j++) {
        int n = n0 + tx * 4 + j;
        float4 r;
        r.x = acc[0][j] + bias[0];
        r.y = acc[1][j] + bias[1];
        r.z = acc[2][j] + bias[2];
        r.w = acc[3][j] + bias[3];
        *(float4*)&g_feat[(size_t)n * C2 + o0 + ty * 4] = r;
    }
}

// ---------------------------------------------------------------------------
// Normalize: rf = feat / max(||feat||, 1e-12); fp32 rf + fp16 hi/lo split.
// ---------------------------------------------------------------------------
__global__ void normalize_kernel() {
    const int n = blockIdx.x;
    const int c = threadIdx.x;
    float v = g_feat[(size_t)n * C2 + c];
    float s = v * v;
#pragma unroll
    for (int off = 16; off; off >>= 1) s += __shfl_xor_sync(0xffffffffu, s, off);
    __shared__ float ws[4];
    if ((c & 31) == 0) ws[c >> 5] = s;
    __syncthreads();
    float tot = ws[0] + ws[1] + ws[2] + ws[3];
    float norm = sqrtf(tot);
    float nf = v / fmaxf(norm, 1e-12f);
    g_rf[(size_t)n * C2 + c] = nf;
    __half hi = __float2half_rn(nf);
    g_hih[(size_t)n * C2 + c] = hi;
    g_loh[(size_t)n * C2 + c] = __float2half_rn(nf - __half2float(hi));
}

// ---------------------------------------------------------------------------
// Top-2 insert with jax top_k tie-breaking (equal value -> lower index).
// ---------------------------------------------------------------------------
__device__ __forceinline__ void ins2(float v, int j,
                                     float& v1, int& i1, float& v2, int& i2) {
    if (v > v1 || (v == v1 && j < i1)) {
        v2 = v1; i2 = i1; v1 = v; i1 = j;
    } else if (v > v2 || (v == v2 && j < i2)) {
        v2 = v; i2 = j;
    }
}

// ---------------------------------------------------------------------------
// Tensor-core (mma.sync fp16 3-term) similarity + top-2.
// Round-5 shape (16 warps/SM) + phase-reordered inner loop for 8-chain ILP:
//   per k-step: al <- smem (A-lo streamed);  bh[16] <- 4x LDSM;
//   8x MMA a_hi*bh  -> 8 independent chains
//   8x MMA al  *bh  -> 8 independent chains
//   bl -> same regs; 8x MMA a_hi*bl
// Grid: (72 i-tiles, 2 j-halves, 2 batches) = 288 CTAs -> 2 CTAs/SM.
// Smem/CTA: A-lo resident 32KB + B double buffer 2x32KB = 96KB.
// D = Ah*Bh' + Al*Bh' + Ah*Bl'  (fp32 accum) — error ~3e-7.
// ---------------------------------------------------------------------------
#define JT    64
#define JHALF (NB / 2)             // 4608
#define NTJ2  (JHALF / JT)         // 72
#define ALO_BYTES 32768            // A-lo resident: 128 rows x 256B
#define BUFB  32768                // one B buffer: hi 16KB + lo 16KB
#define SIM_SMEM (ALO_BYTES + 2 * BUFB)   // 96KB

__device__ __forceinline__ uint32_t sw_off(int r, int c) {
    // row r (256B rows), 16B chunk c, XOR swizzle on chunk index
    return (uint32_t)(r * 256 + ((c ^ (r & 7)) << 4));
}

__global__ void __launch_bounds__(256, 2) sim_mma_kernel() {
    extern __shared__ __align__(1024) char sm[];
    const int t = threadIdx.x;
    const int w = t >> 5, l = t & 31;
    const int jh = blockIdx.y;
    const int b  = blockIdx.z;
    const int i0 = blockIdx.x * 128;
    const int jbase = jh * JHALF;
    const __half* Hsrc = g_hih + (size_t)b * NB * C2;
    const __half* Lsrc = g_loh + (size_t)b * NB * C2;
    const uint32_t sbA = smem_u32(sm);          // A-lo resident region
    const uint32_t bb0 = sbA + ALO_BYTES;       // B buffers

    // ---- Stage A-lo (resident) + A-hi (temporarily in B region) ----
#pragma unroll
    for (int e = 0; e < 8; e++) {
        int id = e * 256 + t;          // 0..2047 : 128 rows x 16 chunks
        int r = id >> 4, c = id & 15;
        uint32_t o = sw_off(r, c);
        CP16(sbA + o, (const char*)(Lsrc + (size_t)(i0 + r) * C2) + c * 16);
        CP16(bb0 + o, (const char*)(Hsrc + (size_t)(i0 + r) * C2) + c * 16);
    }
    CPCOMMIT(); CPWAIT0();
    __syncthreads();

    // ---- A-hi fragments (register resident): a_hi[ks][4] ----
    const int sub = l >> 3;
    const int arl = ((sub & 1) << 3) + (l & 7);
    const int cb  = sub >> 1;
    const int ar  = w * 16 + arl;
    uint32_t a_hi[8][4];
#pragma unroll
    for (int ks = 0; ks < 8; ks++) {
        uint32_t ad = bb0 + sw_off(ar, ks * 2 + cb);
        LDSM4(a_hi[ks][0], a_hi[ks][1], a_hi[ks][2], a_hi[ks][3], ad);
    }
    __syncthreads();   // B region free for streaming now

    // B-tile ldmatrix address pieces (per thread)
    const int brn = ((sub >> 1) << 3) + (l & 7);   // row within 16-row group
    const int bcb = sub & 1;                       // k-chunk select

    // ---- prefetch B tile 0 into buffer 0 ----
#pragma unroll
    for (int e = 0; e < 4; e++) {
        int id = e * 256 + t;      // 0..1023 : 64 rows x 16 chunks
        int r = id >> 4, c = id & 15;
        uint32_t o = sw_off(r, c);
        CP16(bb0 + o,         (const char*)(Hsrc + (size_t)(jbase + r) * C2) + c * 16);
        CP16(bb0 + 16384 + o, (const char*)(Lsrc + (size_t)(jbase + r) * C2) + c * 16);
    }
    CPCOMMIT();

    // per-thread running top-2 for two rows: row_a = w*16 + l/4, row_b = +8
    float v1a = -INFINITY, v2a = -INFINITY, v1b = -INFINITY, v2b = -INFINITY;
    int   i1a = 0x7fffffff, i2a = 0x7fffffff, i1b = 0x7fffffff, i2b = 0x7fffffff;

    for (int jt = 0; jt < NTJ2; jt++) {
        CPWAIT0();
        __syncthreads();

        // prefetch next tile into other buffer (overlaps compute)
        if (jt + 1 < NTJ2) {
            const int j0n = jbase + (jt + 1) * JT;
            const uint32_t bo = bb0 + (uint32_t)((jt + 1) & 1) * BUFB;
#pragma unroll
            for (int e = 0; e < 4; e++) {
                int id = e * 256 + t;
                int r = id >> 4, c = id & 15;
                uint32_t o = bo + sw_off(r, c);
                CP16(o,         (const char*)(Hsrc + (size_t)(j0n + r) * C2) + c * 16);
                CP16(o + 16384, (const char*)(Lsrc + (size_t)(j0n + r) * C2) + c * 16);
            }
            CPCOMMIT();
        }

        const uint32_t bo = bb0 + (uint32_t)(jt & 1) * BUFB;
        float acc[8][4];
#pragma unroll
        for (int nf = 0; nf < 8; nf++)
#pragma unroll
            for (int q = 0; q < 4; q++) acc[nf][q] = 0.f;

#pragma unroll
        for (int ks = 0; ks < 8; ks++) {
            const int ck = ks * 2;
            // stream A-lo fragment for this k-step
            uint32_t al[4];
            LDSM4(al[0], al[1], al[2], al[3], sbA + sw_off(ar, ck + cb));
            // load all 4 B-hi fragments (16 regs)
            uint32_t bf[16];
#pragma unroll
            for (int nb = 0; nb < 4; nb++) {
                uint32_t ad = bo + sw_off(nb * 16 + brn, ck + bcb);
                LDSM4(bf[4 * nb], bf[4 * nb + 1], bf[4 * nb + 2], bf[4 * nb + 3], ad);
            }
            // phase 1: 8 independent chains (a_hi x bh)
#pragma unroll
            for (int nf = 0; nf < 8; nf++) MMA16816(acc[nf], a_hi[ks], bf + 2 * nf);
            // phase 2: 8 independent chains (a_lo x bh)
#pragma unroll
            for (int nf = 0; nf < 8; nf++) MMA16816(acc[nf], al, bf + 2 * nf);
            // reload same regs with B-lo fragments
#pragma unroll
            for (int nb = 0; nb < 4; nb++) {
                uint32_t ad = bo + 16384 + sw_off(nb * 16 + brn, ck + bcb);
                LDSM4(bf[4 * nb], bf[4 * nb + 1], bf[4 * nb + 2], bf[4 * nb + 3], ad);
            }
            // phase 3: 8 independent chains (a_hi x bl)
#pragma unroll
            for (int nf = 0; nf < 8; nf++) MMA16816(acc[nf], a_hi[ks], bf + 2 * nf);
        }

        // ---- fold tile into running top-2 (guarded by max-tree) ----
        const int cbase = jbase + jt * JT + (l & 3) * 2;
        float mA = fmaxf(acc[0][0], acc[0][1]);
        float mB = fmaxf(acc[0][2], acc[0][3]);
#pragma unroll
        for (int nf = 1; nf < 8; nf++) {
            mA = fmaxf(mA, fmaxf(acc[nf][0], acc[nf][1]));
            mB = fmaxf(mB, fmaxf(acc[nf][2], acc[nf][3]));
        }
        if (mA >= v2a) {
#pragma unroll
            for (int nf = 0; nf < 8; nf++) {
                ins2(acc[nf][0], cbase + nf * 8,     v1a, i1a, v2a, i2a);
                ins2(acc[nf][1], cbase + nf * 8 + 1, v1a, i1a, v2a, i2a);
            }
        }
        if (mB >= v2b) {
#pragma unroll
            for (int nf = 0; nf < 8; nf++) {
                ins2(acc[nf][2], cbase + nf * 8,     v1b, i1b, v2b, i2b);
                ins2(acc[nf][3], cbase + nf * 8 + 1, v1b, i1b, v2b, i2b);
            }
        }
    }

    // ---- merge across the 4 lanes (l&3) sharing each row ----
#pragma unroll
    for (int off = 1; off <= 2; off <<= 1) {
        float ov1 = __shfl_xor_sync(0xffffffffu, v1a, off);
        int   oi1 = __shfl_xor_sync(0xffffffffu, i1a, off);
        float ov2 = __shfl_xor_sync(0xffffffffu, v2a, off);
        int   oi2 = __shfl_xor_sync(0xffffffffu, i2a, off);
        ins2(ov1, oi1, v1a, i1a, v2a, i2a);
        ins2(ov2, oi2, v1a, i1a, v2a, i2a);
        ov1 = __shfl_xor_sync(0xffffffffu, v1b, off);
        oi1 = __shfl_xor_sync(0xffffffffu, i1b, off);
        ov2 = __shfl_xor_sync(0xffffffffu, v2b, off);
        oi2 = __shfl_xor_sync(0xffffffffu, i2b, off);
        ins2(ov1, oi1, v1b, i1b, v2b, i2b);
        ins2(ov2, oi2, v1b, i1b, v2b, i2b);
    }
    if ((l & 3) == 0) {
        const int rowa = b * NB + i0 + w * 16 + (l >> 2);
        const int rowb = rowa + 8;
        const size_t pa = ((size_t)jh * NPIX + rowa) * 2;
        const size_t pb = ((size_t)jh * NPIX + rowb) * 2;
        g_t2v[pa]     = v1a; g_t2i[pa]     = i1a;
        g_t2v[pa + 1] = v2a; g_t2i[pa + 1] = i2a;
        g_t2v[pb]     = v1b; g_t2i[pb]     = i1b;
        g_t2v[pb + 1] = v2b; g_t2i[pb + 1] = i2b;
    }
}

// ---------------------------------------------------------------------------
// Merge j-halves + distance + mask (exact fp32 recompute, matches reference).
// ---------------------------------------------------------------------------
__global__ void dist_kernel(float* __restrict__ out) {
    const int gw   = (int)((blockIdx.x * blockDim.x + threadIdx.x) >> 5);
    const int lane = threadIdx.x & 31;
    if (gw >= NPIX) return;
    const int b = gw / NB;
    int nn = 0;
    if (lane == 0) {
        float v1 = -INFINITY, v2 = -INFINITY;
        int   i1 = 0x7fffffff, i2 = 0x7fffffff;
#pragma unroll
        for (int h = 0; h < 2; h++) {
            const size_t p = ((size_t)h * NPIX + gw) * 2;
            ins2(g_t2v[p],     g_t2i[p],     v1, i1, v2, i2);
            ins2(g_t2v[p + 1], g_t2i[p + 1], v1, i1, v2, i2);
        }
        nn = i2;
    }
    nn = __shfl_sync(0xffffffffu, nn, 0);
    const float* a = g_rf + (size_t)gw * C2;
    const float* c = g_rf + (size_t)(b * NB + nn) * C2;
    float4 av = *(const float4*)&a[lane * 4];
    float4 cv = *(const float4*)&c[lane * 4];
    float dx = av.x - cv.x, dy = av.y - cv.y, dz = av.z - cv.z, dw = av.w - cv.w;
    float s = dx * dx + dy * dy + dz * dz + dw * dw;
#pragma unroll
    for (int off = 16; off; off >>= 1) s += __shfl_xor_sync(0xffffffffu, s, off);
    if (lane == 0) {
        float d = sqrtf(s);
        out[NPIX + gw] = d;
        out[gw] = (d > MASK_THR) ? 1.0f : 0.0f;
    }
}

// ---------------------------------------------------------------------------
extern "C" void kernel_launch(void* const* d_in, const int* in_sizes, int n_in,
                              void* d_out, int out_size) {
    const float* features = (const float*)d_in[0];
    const float* W1 = (const float*)d_in[1];
    const float* b1 = (const float*)d_in[2];
    const float* W2 = (const float*)d_in[3];
    const float* b2 = (const float*)d_in[4];
    float* out = (float*)d_out;

    cudaFuncSetAttribute(sim_mma_kernel,
                         cudaFuncAttributeMaxDynamicSharedMemorySize, SIM_SMEM);

    gemm1_kernel<<<dim3(NPIX / 64, C1 / 64), 256>>>(features, W1, b1);
    gemm2_kernel<<<dim3(NPIX / 64, C2 / 64), 256>>>(W2, b2);
    normalize_kernel<<<NPIX, 128>>>();
    sim_mma_kernel<<<dim3(NB / 128, 2, BATCH), 256, SIM_SMEM>>>();
    dist_kernel<<<(NPIX * 32 + 255) / 256, 256>>>(out);
}